// round 14
// baseline (speedup 1.0000x reference)
#include <cuda_runtime.h>
#include <cuda_bf16.h>
#include <stdint.h>
#include <math.h>

#define DM    1024
#define BATCH 8
#define SEQ   2048
#define NH    16
#define HD    64
#define MTOT  (BATCH * SEQ)     // 16384
#define NCHUNK 32               // K chunks of 32

// ---------------- scratch ----------------
__device__ float    g_proj[(size_t)3 * MTOT * DM];   // 192MB
__device__ float    g_concat[(size_t)MTOT * DM];     // 64MB
// W fragment-order pack: [nblk(8)][kc(32)][kk(2)][nb(16)][lane(32)][kh(2)] u32
__device__ uint32_t g_Wp_hi[(size_t)8 * 32 * 2048];  // 2MB
__device__ uint32_t g_Wp_lo[(size_t)8 * 32 * 2048];  // 2MB

// ---------------- helpers ----------------
__device__ __forceinline__ void mma16816(float* c, const uint32_t* a, const uint32_t* b) {
    asm volatile("mma.sync.aligned.m16n8k16.row.col.f32.bf16.bf16.f32 "
                 "{%0,%1,%2,%3}, {%4,%5,%6,%7}, {%8,%9}, {%0,%1,%2,%3};"
                 : "+f"(c[0]), "+f"(c[1]), "+f"(c[2]), "+f"(c[3])
                 : "r"(a[0]), "r"(a[1]), "r"(a[2]), "r"(a[3]), "r"(b[0]), "r"(b[1]));
}
__device__ __forceinline__ uint32_t pack_bf2(float a, float b) {
    __nv_bfloat162 t = __floats2bfloat162_rn(a, b);
    return *reinterpret_cast<uint32_t*>(&t);
}
__device__ __forceinline__ void split2(float2 p, uint32_t& hi, uint32_t& lo) {
    float hx = __bfloat162float(__float2bfloat16(p.x));
    float hy = __bfloat162float(__float2bfloat16(p.y));
    hi = pack_bf2(hx, hy);
    lo = pack_bf2(p.x - hx, p.y - hy);
}

// ---------------- W split + fragment-order pack ----------------
__global__ __launch_bounds__(256)
void convert_w(const float* __restrict__ W)
{
    int i = blockIdx.x * 256 + threadIdx.x;   // float4 index, 262144
    int n = i >> 8;
    int f = i & 255;
    float4 x = reinterpret_cast<const float4*>(W)[i];
    const int nblk = n >> 7, nb = (n >> 3) & 15, gg = n & 7;
#pragma unroll
    for (int j = 0; j < 2; ++j) {
        int p  = 2 * f + j;                   // kpair 0..511
        int kc = p >> 4;
        int kk = (p >> 3) & 1;
        int w  = p & 7;
        int tq = w & 3;
        int kh = w >> 2;
        size_t flat = (size_t)(nblk * 32 + kc) * 2048
                    + (size_t)kk * 1024 + nb * 64 + (gg * 4 + tq) * 2 + kh;
        uint32_t hi, lo;
        split2(j ? make_float2(x.z, x.w) : make_float2(x.x, x.y), hi, lo);
        g_Wp_hi[flat] = hi;
        g_Wp_lo[flat] = lo;
    }
}

// ---------------- GEMM: CTA 128x128, 256 thr, warp 64x32, BK=32, double-buffered ----------------
#define AP 24                 // A smem row pitch (u32)
#define ST_A  (128 * AP)      // 3072 u32 per A plane
#define OFF_AL 3072
#define OFF_BH 6144
#define OFF_BL 8192
#define ST_STAGE 10240        // u32 per stage (40KB)
#define SMEM_DYN (2 * ST_STAGE * 4)   // 80KB

__device__ __forceinline__ void gemm_body(const float* __restrict__ Arow,
                                          const float* __restrict__ bias,
                                          float* __restrict__ Crow, int nblk)
{
    extern __shared__ uint32_t dsm[];

    const int tid  = threadIdx.x;
    const int wid  = tid >> 5;            // 0..7
    const int lane = tid & 31;
    const int wm   = (wid & 1) * 64;
    const int wnb  = (wid >> 1) * 4;
    const int g    = lane >> 2;
    const int tq   = lane & 3;

    const uint32_t* WH = g_Wp_hi + (size_t)nblk * 32 * 2048;
    const uint32_t* WL = g_Wp_lo + (size_t)nblk * 32 * 2048;

    // loader mapping
    const int ra0 = tid >> 3;
    const int qa  = tid & 7;
    const int kkL = qa >> 2;
    const int w0  = 2 * (qa & 3);
    const int sL0 = (w0 & 3) * 2 + (w0 >> 2);
    const int sL1 = ((w0 + 1) & 3) * 2 + ((w0 + 1) >> 2);

    float acc[4][4][4];
#pragma unroll
    for (int i = 0; i < 4; ++i)
#pragma unroll
        for (int j = 0; j < 4; ++j)
#pragma unroll
            for (int l = 0; l < 4; ++l) acc[i][j][l] = 0.f;

    float4 pa[4];
    uint4  pbh[2], pbl[2];

#define PREF(kc) do { \
    _Pragma("unroll") \
    for (int j = 0; j < 4; ++j) \
        pa[j] = *reinterpret_cast<const float4*>(Arow + (size_t)(ra0 + j * 32) * DM + (kc) * 32 + qa * 4); \
    _Pragma("unroll") \
    for (int j = 0; j < 2; ++j) { \
        pbh[j] = *reinterpret_cast<const uint4*>(WH + (size_t)(kc) * 2048 + j * 1024 + tid * 4); \
        pbl[j] = *reinterpret_cast<const uint4*>(WL + (size_t)(kc) * 2048 + j * 1024 + tid * 4); \
    } } while (0)

#define STS(st) do { \
    uint32_t* sb = dsm + (st) * ST_STAGE; \
    _Pragma("unroll") \
    for (int j = 0; j < 4; ++j) { \
        int r = ra0 + j * 32; \
        uint32_t h0, l0, h1, l1; \
        split2(make_float2(pa[j].x, pa[j].y), h0, l0); \
        split2(make_float2(pa[j].z, pa[j].w), h1, l1); \
        int base = r * AP + kkL * 8; \
        sb[base + sL0] = h0;          sb[base + sL1] = h1; \
        sb[OFF_AL + base + sL0] = l0; sb[OFF_AL + base + sL1] = l1; \
    } \
    _Pragma("unroll") \
    for (int j = 0; j < 2; ++j) { \
        *reinterpret_cast<uint4*>(&sb[OFF_BH + j * 1024 + tid * 4]) = pbh[j]; \
        *reinterpret_cast<uint4*>(&sb[OFF_BL + j * 1024 + tid * 4]) = pbl[j]; \
    } } while (0)

    PREF(0);
    STS(0);
    PREF(1);
    __syncthreads();

    for (int kc = 0; kc < NCHUNK; ++kc) {
        const int buf = kc & 1;
        uint32_t* sb = dsm + buf * ST_STAGE;
        // overlap: store next chunk + prefetch chunk+2 while MMAs run on current
        if (kc + 1 < NCHUNK) STS(buf ^ 1);
        if (kc + 2 < NCHUNK) PREF(kc + 2);

#pragma unroll
        for (int kk = 0; kk < 2; ++kk) {
            uint32_t ah[4][4], al[4][4];
#pragma unroll
            for (int mi = 0; mi < 4; ++mi) {
                int r0 = wm + mi * 16 + g;
                int o0 = r0 * AP + kk * 8 + tq * 2;
                int o1 = (r0 + 8) * AP + kk * 8 + tq * 2;
                uint2 x0 = *reinterpret_cast<const uint2*>(&sb[o0]);            // a0,a2
                uint2 x1 = *reinterpret_cast<const uint2*>(&sb[o1]);            // a1,a3
                uint2 y0 = *reinterpret_cast<const uint2*>(&sb[OFF_AL + o0]);
                uint2 y1 = *reinterpret_cast<const uint2*>(&sb[OFF_AL + o1]);
                ah[mi][0] = x0.x; ah[mi][1] = x1.x; ah[mi][2] = x0.y; ah[mi][3] = x1.y;
                al[mi][0] = y0.x; al[mi][1] = y1.x; al[mi][2] = y0.y; al[mi][3] = y1.y;
            }
#pragma unroll
            for (int np = 0; np < 4; ++np) {
                int ob = kk * 1024 + (wnb + np) * 64 + lane * 2;
                uint2 bhv = *reinterpret_cast<const uint2*>(&sb[OFF_BH + ob]);  // b0,b1
                uint2 blv = *reinterpret_cast<const uint2*>(&sb[OFF_BL + ob]);
                uint32_t bh[2] = { bhv.x, bhv.y };
                uint32_t bl[2] = { blv.x, blv.y };
#pragma unroll
                for (int mi = 0; mi < 4; ++mi) {
                    mma16816(acc[mi][np], ah[mi], bh);
                    mma16816(acc[mi][np], ah[mi], bl);
                    mma16816(acc[mi][np], al[mi], bh);
                }
            }
        }
        __syncthreads();
    }
#undef PREF
#undef STS

    // epilogue
    const int n0 = nblk * 128;
    const int en = tq * 2;
#pragma unroll
    for (int mi = 0; mi < 4; ++mi) {
#pragma unroll
        for (int np = 0; np < 4; ++np) {
            int col = n0 + (wnb + np) * 8 + en;
            float bx = __ldg(bias + col), by = __ldg(bias + col + 1);
            size_t r0 = (size_t)(wm + mi * 16 + g);
            float2 v0 = { acc[mi][np][0] + bx, acc[mi][np][1] + by };
            float2 v1 = { acc[mi][np][2] + bx, acc[mi][np][3] + by };
            *reinterpret_cast<float2*>(Crow + r0 * DM + col)       = v0;
            *reinterpret_cast<float2*>(Crow + (r0 + 8) * DM + col) = v1;
        }
    }
}

__global__ __launch_bounds__(256)
void proj_kernel(const float* __restrict__ q, const float* __restrict__ k,
                 const float* __restrict__ v, const float* __restrict__ bias)
{
    const int bm  = blockIdx.y;        // 0..383
    const int sel = bm >> 7;
    const float* A = (sel == 0) ? q : ((sel == 1) ? k : v);
    const int rowblk = bm & 127;
    gemm_body(A + (size_t)rowblk * 128 * DM, bias,
              g_proj + ((size_t)sel * MTOT + (size_t)rowblk * 128) * DM,
              blockIdx.x);
}

__global__ __launch_bounds__(256)
void final_kernel(const float* __restrict__ bias, float* __restrict__ out)
{
    gemm_body(g_concat + (size_t)blockIdx.y * 128 * DM, bias,
              out + (size_t)blockIdx.y * 128 * DM, blockIdx.x);
}

// ---------------- per-token attention, register-tiled (proven) ----------------
#define SLP 68

__global__ __launch_bounds__(256)
void attn_kernel()
{
    const int pos = blockIdx.x;
    const int b   = pos >> 11;
    const int s   = pos & 2047;

    __shared__ float sq[DM];
    __shared__ float sk[DM];
    __shared__ float svT[DM];
    __shared__ float sL[HD * SLP];

    const int tid = threadIdx.x;
    const float* baseq = g_proj + (size_t)pos * DM;
    const float* basek = g_proj + ((size_t)MTOT + pos) * DM;
    const float* basev = g_proj + ((size_t)2 * MTOT + pos) * DM;

    reinterpret_cast<float4*>(sq)[tid] = reinterpret_cast<const float4*>(baseq)[tid];
    reinterpret_cast<float4*>(sk)[tid] = reinterpret_cast<const float4*>(basek)[tid];
    {
        float4 vv = reinterpret_cast<const float4*>(basev)[tid];
        int n0 = tid * 4;
        int h  = n0 >> 6;
        int e  = n0 & 63;
        svT[(e + 0) * NH + h] = vv.x;
        svT[(e + 1) * NH + h] = vv.y;
        svT[(e + 2) * NH + h] = vv.z;
        svT[(e + 3) * NH + h] = vv.w;
    }
    __syncthreads();

    {
        const int ty = tid >> 4;
        const int tx = tid & 15;
        float c[4][4];
#pragma unroll
        for (int i = 0; i < 4; ++i)
#pragma unroll
            for (int j = 0; j < 4; ++j) c[i][j] = 0.f;
#pragma unroll
        for (int h = 0; h < 16; ++h) {
            float4 qa = *reinterpret_cast<const float4*>(&sq[h * HD + ty * 4]);
            float4 kb = *reinterpret_cast<const float4*>(&sk[h * HD + tx * 4]);
            const float qv[4] = { qa.x, qa.y, qa.z, qa.w };
            const float kv[4] = { kb.x, kb.y, kb.z, kb.w };
#pragma unroll
            for (int i = 0; i < 4; ++i)
#pragma unroll
                for (int j = 0; j < 4; ++j)
                    c[i][j] += qv[i] * kv[j];
        }
#pragma unroll
        for (int i = 0; i < 4; ++i) {
            float4 v = { c[i][0] * 0.125f, c[i][1] * 0.125f,
                         c[i][2] * 0.125f, c[i][3] * 0.125f };
            *reinterpret_cast<float4*>(&sL[(ty * 4 + i) * SLP + tx * 4]) = v;
        }
    }
    __syncthreads();

    {
        const int row = tid >> 2;
        const int sub = tid & 3;
        float* rp = sL + row * SLP + sub * 16;
        float4 v0 = *reinterpret_cast<float4*>(rp + 0);
        float4 v1 = *reinterpret_cast<float4*>(rp + 4);
        float4 v2 = *reinterpret_cast<float4*>(rp + 8);
        float4 v3 = *reinterpret_cast<float4*>(rp + 12);
        float m = fmaxf(fmaxf(fmaxf(v0.x, v0.y), fmaxf(v0.z, v0.w)),
                        fmaxf(fmaxf(v1.x, v1.y), fmaxf(v1.z, v1.w)));
        m = fmaxf(m, fmaxf(fmaxf(fmaxf(v2.x, v2.y), fmaxf(v2.z, v2.w)),
                           fmaxf(fmaxf(v3.x, v3.y), fmaxf(v3.z, v3.w))));
        m = fmaxf(m, __shfl_xor_sync(0xFFFFFFFFu, m, 1));
        m = fmaxf(m, __shfl_xor_sync(0xFFFFFFFFu, m, 2));
        v0.x = __expf(v0.x - m); v0.y = __expf(v0.y - m);
        v0.z = __expf(v0.z - m); v0.w = __expf(v0.w - m);
        v1.x = __expf(v1.x - m); v1.y = __expf(v1.y - m);
        v1.z = __expf(v1.z - m); v1.w = __expf(v1.w - m);
        v2.x = __expf(v2.x - m); v2.y = __expf(v2.y - m);
        v2.z = __expf(v2.z - m); v2.w = __expf(v2.w - m);
        v3.x = __expf(v3.x - m); v3.y = __expf(v3.y - m);
        v3.z = __expf(v3.z - m); v3.w = __expf(v3.w - m);
        float sum = (v0.x + v0.y + v0.z + v0.w) + (v1.x + v1.y + v1.z + v1.w)
                  + (v2.x + v2.y + v2.z + v2.w) + (v3.x + v3.y + v3.z + v3.w);
        sum += __shfl_xor_sync(0xFFFFFFFFu, sum, 1);
        sum += __shfl_xor_sync(0xFFFFFFFFu, sum, 2);
        float inv = 1.f / sum;
        v0.x *= inv; v0.y *= inv; v0.z *= inv; v0.w *= inv;
        v1.x *= inv; v1.y *= inv; v1.z *= inv; v1.w *= inv;
        v2.x *= inv; v2.y *= inv; v2.z *= inv; v2.w *= inv;
        v3.x *= inv; v3.y *= inv; v3.z *= inv; v3.w *= inv;
        *reinterpret_cast<float4*>(rp + 0)  = v0;
        *reinterpret_cast<float4*>(rp + 4)  = v1;
        *reinterpret_cast<float4*>(rp + 8)  = v2;
        *reinterpret_cast<float4*>(rp + 12) = v3;
    }
    __syncthreads();

    {
        const int d  = tid >> 2;
        const int hq = tid & 3;
        float4 acc = { 0.f, 0.f, 0.f, 0.f };
        const float* lrow = sL + d * SLP;
#pragma unroll 8
        for (int e = 0; e < 64; ++e) {
            float p = lrow[e];
            float4 vv = *reinterpret_cast<const float4*>(&svT[e * NH + hq * 4]);
            acc.x += p * vv.x; acc.y += p * vv.y;
            acc.z += p * vv.z; acc.w += p * vv.w;
        }
        const int srow = s >> 6;
        const int scol = s & 63;
        float* dst = g_concat + (size_t)b * SEQ * DM
                   + (size_t)(d * 32 + srow) * DM + scol * NH + hq * 4;
        *reinterpret_cast<float4*>(dst) = acc;
    }
}

// ---------------------------------------------------------------------------
extern "C" void kernel_launch(void* const* d_in, const int* in_sizes, int n_in,
                              void* d_out, int out_size)
{
    const float* q = (const float*)d_in[0];
    const float* k = (const float*)d_in[1];
    const float* v = (const float*)d_in[2];
    const float* W = (const float*)d_in[3];
    const float* b = (const float*)d_in[4];
    float* out = (float*)d_out;

    cudaFuncSetAttribute(proj_kernel,  cudaFuncAttributeMaxDynamicSharedMemorySize, SMEM_DYN);
    cudaFuncSetAttribute(final_kernel, cudaFuncAttributeMaxDynamicSharedMemorySize, SMEM_DYN);

    convert_w<<<DM * DM / 4 / 256, 256>>>(W);

    proj_kernel<<<dim3(8, 384), 256, SMEM_DYN>>>(q, k, v, b);

    attn_kernel<<<MTOT, 256>>>();

    final_kernel<<<dim3(8, 128), 256, SMEM_DYN>>>(b, out);
}

// round 15
// speedup vs baseline: 1.0165x; 1.0165x over previous
#include <cuda_runtime.h>
#include <cuda_bf16.h>
#include <stdint.h>
#include <math.h>

#define DM    1024
#define BATCH 8
#define SEQ   2048
#define NH    16
#define HD    64
#define MTOT  (BATCH * SEQ)     // 16384
#define NCHUNK 32               // K chunks of 32

// ---------------- scratch ----------------
__device__ float    g_proj[(size_t)3 * MTOT * DM];   // 192MB
__device__ float    g_concat[(size_t)MTOT * DM];     // 64MB
// W fragment-order pack: [nblk(16)][kc(32)][kk(2)][nb(8)][lane(32)][kh(2)] u32
__device__ uint32_t g_Wp_hi[(size_t)16 * 32 * 1024]; // 2MB
__device__ uint32_t g_Wp_lo[(size_t)16 * 32 * 1024]; // 2MB

// ---------------- helpers ----------------
__device__ __forceinline__ void mma16816(float* c, const uint32_t* a, const uint32_t* b) {
    asm volatile("mma.sync.aligned.m16n8k16.row.col.f32.bf16.bf16.f32 "
                 "{%0,%1,%2,%3}, {%4,%5,%6,%7}, {%8,%9}, {%0,%1,%2,%3};"
                 : "+f"(c[0]), "+f"(c[1]), "+f"(c[2]), "+f"(c[3])
                 : "r"(a[0]), "r"(a[1]), "r"(a[2]), "r"(a[3]), "r"(b[0]), "r"(b[1]));
}
__device__ __forceinline__ uint32_t pack_bf2(float a, float b) {
    __nv_bfloat162 t = __floats2bfloat162_rn(a, b);
    return *reinterpret_cast<uint32_t*>(&t);
}
__device__ __forceinline__ void split2(float2 p, uint32_t& hi, uint32_t& lo) {
    float hx = __bfloat162float(__float2bfloat16(p.x));
    float hy = __bfloat162float(__float2bfloat16(p.y));
    hi = pack_bf2(hx, hy);
    lo = pack_bf2(p.x - hx, p.y - hy);
}

// ---------------- W split + fragment-order pack (64-col n-blocks) ----------------
__global__ __launch_bounds__(256)
void convert_w(const float* __restrict__ W)
{
    int i = blockIdx.x * 256 + threadIdx.x;   // float4 index, 262144
    int n = i >> 8;
    int f = i & 255;
    float4 x = reinterpret_cast<const float4*>(W)[i];
    const int nblk = n >> 6, nb = (n >> 3) & 7, gg = n & 7;
#pragma unroll
    for (int j = 0; j < 2; ++j) {
        int p  = 2 * f + j;                   // kpair 0..511
        int kc = p >> 4;
        int kk = (p >> 3) & 1;
        int w  = p & 7;
        int tq = w & 3;
        int kh = w >> 2;
        size_t flat = (size_t)(nblk * 32 + kc) * 1024
                    + (size_t)kk * 512 + nb * 64 + (gg * 4 + tq) * 2 + kh;
        uint32_t hi, lo;
        split2(j ? make_float2(x.z, x.w) : make_float2(x.x, x.y), hi, lo);
        g_Wp_hi[flat] = hi;
        g_Wp_lo[flat] = lo;
    }
}

// ---------------- GEMM: CTA 128x64, 256 thr, warp tile 32x32, BK=32, 2 CTA/SM ----------------
#define AP 24   // A smem row pitch (u32); slots kk*8 + s(w), s(w)=(w&3)*2+(w>>2)

__device__ __forceinline__ void gemm_body(const float* __restrict__ Arow,
                                          const float* __restrict__ bias,
                                          float* __restrict__ Crow, int nblk)
{
    __shared__ uint32_t sAh[128 * AP], sAl[128 * AP];   // 12KB each
    __shared__ uint32_t sBh[1024], sBl[1024];           // 4KB each; 32KB total

    const int tid  = threadIdx.x;
    const int wid  = tid >> 5;            // 0..7
    const int lane = tid & 31;
    const int wm   = (wid & 3) * 32;      // 4 m-groups of 32
    const int wnb  = (wid >> 2) * 4;      // 2 n-groups: nb base 0 or 4
    const int g    = lane >> 2;
    const int tq   = lane & 3;

    const uint32_t* WH = g_Wp_hi + (size_t)nblk * 32 * 1024;
    const uint32_t* WL = g_Wp_lo + (size_t)nblk * 32 * 1024;

    // loader mapping: 4 float4 of A per thread; 1 uint4 of each B plane
    const int ra0 = tid >> 3;             // rows ra0 + j*32
    const int qa  = tid & 7;
    const int kkL = qa >> 2;
    const int w0  = 2 * (qa & 3);
    const int sL0 = (w0 & 3) * 2 + (w0 >> 2);
    const int sL1 = ((w0 + 1) & 3) * 2 + ((w0 + 1) >> 2);

    float acc[2][4][4];
#pragma unroll
    for (int i = 0; i < 2; ++i)
#pragma unroll
        for (int j = 0; j < 4; ++j)
#pragma unroll
            for (int l = 0; l < 4; ++l) acc[i][j][l] = 0.f;

    float4 pa[4];
    uint4  pbh, pbl;

#define PREF(kc) do { \
    _Pragma("unroll") \
    for (int j = 0; j < 4; ++j) \
        pa[j] = *reinterpret_cast<const float4*>(Arow + (size_t)(ra0 + j * 32) * DM + (kc) * 32 + qa * 4); \
    pbh = *reinterpret_cast<const uint4*>(WH + (size_t)(kc) * 1024 + tid * 4); \
    pbl = *reinterpret_cast<const uint4*>(WL + (size_t)(kc) * 1024 + tid * 4); \
    } while (0)

#define STORE() do { \
    _Pragma("unroll") \
    for (int j = 0; j < 4; ++j) { \
        int r = ra0 + j * 32; \
        uint32_t h0, l0, h1, l1; \
        split2(make_float2(pa[j].x, pa[j].y), h0, l0); \
        split2(make_float2(pa[j].z, pa[j].w), h1, l1); \
        int base = r * AP + kkL * 8; \
        sAh[base + sL0] = h0;  sAh[base + sL1] = h1; \
        sAl[base + sL0] = l0;  sAl[base + sL1] = l1; \
    } \
    *reinterpret_cast<uint4*>(&sBh[tid * 4]) = pbh; \
    *reinterpret_cast<uint4*>(&sBl[tid * 4]) = pbl; \
    } while (0)

    PREF(0);

    for (int kc = 0; kc < NCHUNK; ++kc) {
        STORE();
        __syncthreads();
        if (kc + 1 < NCHUNK) PREF(kc + 1);   // LDG hidden behind MMAs

#pragma unroll
        for (int kk = 0; kk < 2; ++kk) {
            uint32_t ah[2][4], al[2][4];
#pragma unroll
            for (int mi = 0; mi < 2; ++mi) {
                int r0 = wm + mi * 16 + g;
                int o0 = r0 * AP + kk * 8 + tq * 2;
                int o1 = (r0 + 8) * AP + kk * 8 + tq * 2;
                uint2 x0 = *reinterpret_cast<const uint2*>(&sAh[o0]);  // a0,a2
                uint2 x1 = *reinterpret_cast<const uint2*>(&sAh[o1]);  // a1,a3
                uint2 y0 = *reinterpret_cast<const uint2*>(&sAl[o0]);
                uint2 y1 = *reinterpret_cast<const uint2*>(&sAl[o1]);
                ah[mi][0] = x0.x; ah[mi][1] = x1.x; ah[mi][2] = x0.y; ah[mi][3] = x1.y;
                al[mi][0] = y0.x; al[mi][1] = y1.x; al[mi][2] = y0.y; al[mi][3] = y1.y;
            }
#pragma unroll
            for (int np = 0; np < 4; ++np) {
                int ob = kk * 512 + (wnb + np) * 64 + lane * 2;
                uint2 bhv = *reinterpret_cast<const uint2*>(&sBh[ob]);  // b0,b1
                uint2 blv = *reinterpret_cast<const uint2*>(&sBl[ob]);
                uint32_t bh[2] = { bhv.x, bhv.y };
                uint32_t bl[2] = { blv.x, blv.y };
#pragma unroll
                for (int mi = 0; mi < 2; ++mi) {
                    mma16816(acc[mi][np], ah[mi], bh);
                    mma16816(acc[mi][np], ah[mi], bl);
                    mma16816(acc[mi][np], al[mi], bh);
                }
            }
        }
        __syncthreads();
    }
#undef PREF
#undef STORE

    // epilogue
    const int n0 = nblk * 64;
    const int en = tq * 2;
#pragma unroll
    for (int mi = 0; mi < 2; ++mi) {
#pragma unroll
        for (int np = 0; np < 4; ++np) {
            int col = n0 + (wnb + np) * 8 + en;
            float bx = __ldg(bias + col), by = __ldg(bias + col + 1);
            size_t r0 = (size_t)(wm + mi * 16 + g);
            float2 v0 = { acc[mi][np][0] + bx, acc[mi][np][1] + by };
            float2 v1 = { acc[mi][np][2] + bx, acc[mi][np][3] + by };
            *reinterpret_cast<float2*>(Crow + r0 * DM + col)       = v0;
            *reinterpret_cast<float2*>(Crow + (r0 + 8) * DM + col) = v1;
        }
    }
}

__global__ __launch_bounds__(256, 2)
void proj_kernel(const float* __restrict__ q, const float* __restrict__ k,
                 const float* __restrict__ v, const float* __restrict__ bias)
{
    const int bm  = blockIdx.y;        // 0..383
    const int sel = bm >> 7;
    const float* A = (sel == 0) ? q : ((sel == 1) ? k : v);
    const int rowblk = bm & 127;
    gemm_body(A + (size_t)rowblk * 128 * DM, bias,
              g_proj + ((size_t)sel * MTOT + (size_t)rowblk * 128) * DM,
              blockIdx.x);
}

__global__ __launch_bounds__(256, 2)
void final_kernel(const float* __restrict__ bias, float* __restrict__ out)
{
    gemm_body(g_concat + (size_t)blockIdx.y * 128 * DM, bias,
              out + (size_t)blockIdx.y * 128 * DM, blockIdx.x);
}

// ---------------- per-token attention, register-tiled (proven) ----------------
#define SLP 68

__global__ __launch_bounds__(256)
void attn_kernel()
{
    const int pos = blockIdx.x;
    const int b   = pos >> 11;
    const int s   = pos & 2047;

    __shared__ float sq[DM];
    __shared__ float sk[DM];
    __shared__ float svT[DM];
    __shared__ float sL[HD * SLP];

    const int tid = threadIdx.x;
    const float* baseq = g_proj + (size_t)pos * DM;
    const float* basek = g_proj + ((size_t)MTOT + pos) * DM;
    const float* basev = g_proj + ((size_t)2 * MTOT + pos) * DM;

    reinterpret_cast<float4*>(sq)[tid] = reinterpret_cast<const float4*>(baseq)[tid];
    reinterpret_cast<float4*>(sk)[tid] = reinterpret_cast<const float4*>(basek)[tid];
    {
        float4 vv = reinterpret_cast<const float4*>(basev)[tid];
        int n0 = tid * 4;
        int h  = n0 >> 6;
        int e  = n0 & 63;
        svT[(e + 0) * NH + h] = vv.x;
        svT[(e + 1) * NH + h] = vv.y;
        svT[(e + 2) * NH + h] = vv.z;
        svT[(e + 3) * NH + h] = vv.w;
    }
    __syncthreads();

    {
        const int ty = tid >> 4;
        const int tx = tid & 15;
        float c[4][4];
#pragma unroll
        for (int i = 0; i < 4; ++i)
#pragma unroll
            for (int j = 0; j < 4; ++j) c[i][j] = 0.f;
#pragma unroll
        for (int h = 0; h < 16; ++h) {
            float4 qa = *reinterpret_cast<const float4*>(&sq[h * HD + ty * 4]);
            float4 kb = *reinterpret_cast<const float4*>(&sk[h * HD + tx * 4]);
            const float qv[4] = { qa.x, qa.y, qa.z, qa.w };
            const float kv[4] = { kb.x, kb.y, kb.z, kb.w };
#pragma unroll
            for (int i = 0; i < 4; ++i)
#pragma unroll
                for (int j = 0; j < 4; ++j)
                    c[i][j] += qv[i] * kv[j];
        }
#pragma unroll
        for (int i = 0; i < 4; ++i) {
            float4 v = { c[i][0] * 0.125f, c[i][1] * 0.125f,
                         c[i][2] * 0.125f, c[i][3] * 0.125f };
            *reinterpret_cast<float4*>(&sL[(ty * 4 + i) * SLP + tx * 4]) = v;
        }
    }
    __syncthreads();

    {
        const int row = tid >> 2;
        const int sub = tid & 3;
        float* rp = sL + row * SLP + sub * 16;
        float4 v0 = *reinterpret_cast<float4*>(rp + 0);
        float4 v1 = *reinterpret_cast<float4*>(rp + 4);
        float4 v2 = *reinterpret_cast<float4*>(rp + 8);
        float4 v3 = *reinterpret_cast<float4*>(rp + 12);
        float m = fmaxf(fmaxf(fmaxf(v0.x, v0.y), fmaxf(v0.z, v0.w)),
                        fmaxf(fmaxf(v1.x, v1.y), fmaxf(v1.z, v1.w)));
        m = fmaxf(m, fmaxf(fmaxf(fmaxf(v2.x, v2.y), fmaxf(v2.z, v2.w)),
                           fmaxf(fmaxf(v3.x, v3.y), fmaxf(v3.z, v3.w))));
        m = fmaxf(m, __shfl_xor_sync(0xFFFFFFFFu, m, 1));
        m = fmaxf(m, __shfl_xor_sync(0xFFFFFFFFu, m, 2));
        v0.x = __expf(v0.x - m); v0.y = __expf(v0.y - m);
        v0.z = __expf(v0.z - m); v0.w = __expf(v0.w - m);
        v1.x = __expf(v1.x - m); v1.y = __expf(v1.y - m);
        v1.z = __expf(v1.z - m); v1.w = __expf(v1.w - m);
        v2.x = __expf(v2.x - m); v2.y = __expf(v2.y - m);
        v2.z = __expf(v2.z - m); v2.w = __expf(v2.w - m);
        v3.x = __expf(v3.x - m); v3.y = __expf(v3.y - m);
        v3.z = __expf(v3.z - m); v3.w = __expf(v3.w - m);
        float sum = (v0.x + v0.y + v0.z + v0.w) + (v1.x + v1.y + v1.z + v1.w)
                  + (v2.x + v2.y + v2.z + v2.w) + (v3.x + v3.y + v3.z + v3.w);
        sum += __shfl_xor_sync(0xFFFFFFFFu, sum, 1);
        sum += __shfl_xor_sync(0xFFFFFFFFu, sum, 2);
        float inv = 1.f / sum;
        v0.x *= inv; v0.y *= inv; v0.z *= inv; v0.w *= inv;
        v1.x *= inv; v1.y *= inv; v1.z *= inv; v1.w *= inv;
        v2.x *= inv; v2.y *= inv; v2.z *= inv; v2.w *= inv;
        v3.x *= inv; v3.y *= inv; v3.z *= inv; v3.w *= inv;
        *reinterpret_cast<float4*>(rp + 0)  = v0;
        *reinterpret_cast<float4*>(rp + 4)  = v1;
        *reinterpret_cast<float4*>(rp + 8)  = v2;
        *reinterpret_cast<float4*>(rp + 12) = v3;
    }
    __syncthreads();

    {
        const int d  = tid >> 2;
        const int hq = tid & 3;
        float4 acc = { 0.f, 0.f, 0.f, 0.f };
        const float* lrow = sL + d * SLP;
#pragma unroll 8
        for (int e = 0; e < 64; ++e) {
            float p = lrow[e];
            float4 vv = *reinterpret_cast<const float4*>(&svT[e * NH + hq * 4]);
            acc.x += p * vv.x; acc.y += p * vv.y;
            acc.z += p * vv.z; acc.w += p * vv.w;
        }
        const int srow = s >> 6;
        const int scol = s & 63;
        float* dst = g_concat + (size_t)b * SEQ * DM
                   + (size_t)(d * 32 + srow) * DM + scol * NH + hq * 4;
        *reinterpret_cast<float4*>(dst) = acc;
    }
}

// ---------------------------------------------------------------------------
extern "C" void kernel_launch(void* const* d_in, const int* in_sizes, int n_in,
                              void* d_out, int out_size)
{
    const float* q = (const float*)d_in[0];
    const float* k = (const float*)d_in[1];
    const float* v = (const float*)d_in[2];
    const float* W = (const float*)d_in[3];
    const float* b = (const float*)d_in[4];
    float* out = (float*)d_out;

    convert_w<<<DM * DM / 4 / 256, 256>>>(W);

    proj_kernel<<<dim3(16, 384), 256>>>(q, k, v, b);

    attn_kernel<<<MTOT, 256>>>();

    final_kernel<<<dim3(16, 128), 256>>>(b, out);
}

// round 16
// speedup vs baseline: 1.1075x; 1.0895x over previous
#include <cuda_runtime.h>
#include <cuda_bf16.h>
#include <stdint.h>
#include <math.h>

#define DM    1024
#define BATCH 8
#define SEQ   2048
#define NH    16
#define HD    64
#define MTOT  (BATCH * SEQ)     // 16384
#define NCHUNK 32               // K chunks of 32

// ---------------- scratch ----------------
__device__ float    g_proj[(size_t)3 * MTOT * DM];   // 192MB
__device__ float    g_concat[(size_t)MTOT * DM];     // 64MB
// W fragment-order pack: [nblk(8)][kc(32)][kk(2)][nb(16)][lane(32)][kh(2)] u32
__device__ uint32_t g_Wp_hi[(size_t)8 * 32 * 2048];  // 2MB
__device__ uint32_t g_Wp_lo[(size_t)8 * 32 * 2048];  // 2MB

// ---------------- helpers ----------------
__device__ __forceinline__ void mma16816(float* c, const uint32_t* a, const uint32_t* b) {
    asm volatile("mma.sync.aligned.m16n8k16.row.col.f32.bf16.bf16.f32 "
                 "{%0,%1,%2,%3}, {%4,%5,%6,%7}, {%8,%9}, {%0,%1,%2,%3};"
                 : "+f"(c[0]), "+f"(c[1]), "+f"(c[2]), "+f"(c[3])
                 : "r"(a[0]), "r"(a[1]), "r"(a[2]), "r"(a[3]), "r"(b[0]), "r"(b[1]));
}
__device__ __forceinline__ uint32_t pack_bf2(float a, float b) {
    __nv_bfloat162 t = __floats2bfloat162_rn(a, b);
    return *reinterpret_cast<uint32_t*>(&t);
}
__device__ __forceinline__ void split2(float2 p, uint32_t& hi, uint32_t& lo) {
    float hx = __bfloat162float(__float2bfloat16(p.x));
    float hy = __bfloat162float(__float2bfloat16(p.y));
    hi = pack_bf2(hx, hy);
    lo = pack_bf2(p.x - hx, p.y - hy);
}

// ---------------- W split + fragment-order pack ----------------
__global__ __launch_bounds__(256)
void convert_w(const float* __restrict__ W)
{
    int i = blockIdx.x * 256 + threadIdx.x;   // float4 index, 262144
    int n = i >> 8;
    int f = i & 255;
    float4 x = reinterpret_cast<const float4*>(W)[i];
    const int nblk = n >> 7, nb = (n >> 3) & 15, gg = n & 7;
#pragma unroll
    for (int j = 0; j < 2; ++j) {
        int p  = 2 * f + j;                   // kpair 0..511
        int kc = p >> 4;
        int kk = (p >> 3) & 1;
        int w  = p & 7;
        int tq = w & 3;
        int kh = w >> 2;
        size_t flat = (size_t)(nblk * 32 + kc) * 2048
                    + (size_t)kk * 1024 + nb * 64 + (gg * 4 + tq) * 2 + kh;
        uint32_t hi, lo;
        split2(j ? make_float2(x.z, x.w) : make_float2(x.x, x.y), hi, lo);
        g_Wp_hi[flat] = hi;
        g_Wp_lo[flat] = lo;
    }
}

// ---------------- GEMM: CTA 128x128, 256 thr, warp tile 64x32, BK=32 ----------------
#define AP 24   // A smem row pitch (u32); slots kk*8 + s(w), s(w)=(w&3)*2+(w>>2)

__device__ __forceinline__ void gemm_body(const float* __restrict__ Arow,
                                          const float* __restrict__ bias,
                                          float* __restrict__ Crow, int nblk)
{
    __shared__ uint32_t sAh[128 * AP], sAl[128 * AP];   // 12KB each
    __shared__ uint32_t sBh[2048], sBl[2048];           // 8KB each; 40KB total

    const int tid  = threadIdx.x;
    const int wid  = tid >> 5;            // 0..7
    const int lane = tid & 31;
    const int wm   = (wid & 1) * 64;      // 2 m-groups of 64
    const int wnb  = (wid >> 1) * 4;      // n-group: 4 nb blocks (32 cols)
    const int g    = lane >> 2;
    const int tq   = lane & 3;

    const uint32_t* WH = g_Wp_hi + (size_t)nblk * 32 * 2048;
    const uint32_t* WL = g_Wp_lo + (size_t)nblk * 32 * 2048;

    // loader mapping: 4 float4 of A per thread, 2 uint4 of each B plane
    const int ra0 = tid >> 3;
    const int qa  = tid & 7;
    const int kkL = qa >> 2;
    const int w0  = 2 * (qa & 3);
    const int sL0 = (w0 & 3) * 2 + (w0 >> 2);
    const int sL1 = ((w0 + 1) & 3) * 2 + ((w0 + 1) >> 2);

    float acc[4][4][4];
#pragma unroll
    for (int i = 0; i < 4; ++i)
#pragma unroll
        for (int j = 0; j < 4; ++j)
#pragma unroll
            for (int l = 0; l < 4; ++l) acc[i][j][l] = 0.f;

    float4 pa[4];
    uint4  pbh[2], pbl[2];

#define PREF(kc) do { \
    _Pragma("unroll") \
    for (int j = 0; j < 4; ++j) \
        pa[j] = *reinterpret_cast<const float4*>(Arow + (size_t)(ra0 + j * 32) * DM + (kc) * 32 + qa * 4); \
    _Pragma("unroll") \
    for (int j = 0; j < 2; ++j) { \
        pbh[j] = *reinterpret_cast<const uint4*>(WH + (size_t)(kc) * 2048 + j * 1024 + tid * 4); \
        pbl[j] = *reinterpret_cast<const uint4*>(WL + (size_t)(kc) * 2048 + j * 1024 + tid * 4); \
    } } while (0)

#define STORE() do { \
    _Pragma("unroll") \
    for (int j = 0; j < 4; ++j) { \
        int r = ra0 + j * 32; \
        uint32_t h0, l0, h1, l1; \
        split2(make_float2(pa[j].x, pa[j].y), h0, l0); \
        split2(make_float2(pa[j].z, pa[j].w), h1, l1); \
        int base = r * AP + kkL * 8; \
        sAh[base + sL0] = h0;  sAh[base + sL1] = h1; \
        sAl[base + sL0] = l0;  sAl[base + sL1] = l1; \
    } \
    _Pragma("unroll") \
    for (int j = 0; j < 2; ++j) { \
        *reinterpret_cast<uint4*>(&sBh[j * 1024 + tid * 4]) = pbh[j]; \
        *reinterpret_cast<uint4*>(&sBl[j * 1024 + tid * 4]) = pbl[j]; \
    } } while (0)

    PREF(0);

    for (int kc = 0; kc < NCHUNK; ++kc) {
        STORE();
        __syncthreads();
        if (kc + 1 < NCHUNK) PREF(kc + 1);   // LDG hidden behind MMAs

#pragma unroll
        for (int kk = 0; kk < 2; ++kk) {
            // ---- load all fragments for this k16 ----
            uint32_t ah[4][4], al[4][4];
#pragma unroll
            for (int mi = 0; mi < 4; ++mi) {
                int r0 = wm + mi * 16 + g;
                int o0 = r0 * AP + kk * 8 + tq * 2;
                int o1 = (r0 + 8) * AP + kk * 8 + tq * 2;
                uint2 x0 = *reinterpret_cast<const uint2*>(&sAh[o0]);  // a0,a2
                uint2 x1 = *reinterpret_cast<const uint2*>(&sAh[o1]);  // a1,a3
                uint2 y0 = *reinterpret_cast<const uint2*>(&sAl[o0]);
                uint2 y1 = *reinterpret_cast<const uint2*>(&sAl[o1]);
                ah[mi][0] = x0.x; ah[mi][1] = x1.x; ah[mi][2] = x0.y; ah[mi][3] = x1.y;
                al[mi][0] = y0.x; al[mi][1] = y1.x; al[mi][2] = y0.y; al[mi][3] = y1.y;
            }
            uint32_t bh[4][2], bl[4][2];
#pragma unroll
            for (int np = 0; np < 4; ++np) {
                int ob = kk * 1024 + (wnb + np) * 64 + lane * 2;
                uint2 bhv = *reinterpret_cast<const uint2*>(&sBh[ob]);
                uint2 blv = *reinterpret_cast<const uint2*>(&sBl[ob]);
                bh[np][0] = bhv.x; bh[np][1] = bhv.y;
                bl[np][0] = blv.x; bl[np][1] = blv.y;
            }
            // ---- pass-major MMA order: acc reuse distance = 16 ----
#pragma unroll
            for (int np = 0; np < 4; ++np)
#pragma unroll
                for (int mi = 0; mi < 4; ++mi)
                    mma16816(acc[mi][np], ah[mi], bh[np]);
#pragma unroll
            for (int np = 0; np < 4; ++np)
#pragma unroll
                for (int mi = 0; mi < 4; ++mi)
                    mma16816(acc[mi][np], ah[mi], bl[np]);
#pragma unroll
            for (int np = 0; np < 4; ++np)
#pragma unroll
                for (int mi = 0; mi < 4; ++mi)
                    mma16816(acc[mi][np], al[mi], bh[np]);
        }
        __syncthreads();
    }
#undef PREF
#undef STORE

    // epilogue
    const int n0 = nblk * 128;
    const int en = tq * 2;
#pragma unroll
    for (int mi = 0; mi < 4; ++mi) {
#pragma unroll
        for (int np = 0; np < 4; ++np) {
            int col = n0 + (wnb + np) * 8 + en;
            float bx = __ldg(bias + col), by = __ldg(bias + col + 1);
            size_t r0 = (size_t)(wm + mi * 16 + g);
            float2 v0 = { acc[mi][np][0] + bx, acc[mi][np][1] + by };
            float2 v1 = { acc[mi][np][2] + bx, acc[mi][np][3] + by };
            *reinterpret_cast<float2*>(Crow + r0 * DM + col)       = v0;
            *reinterpret_cast<float2*>(Crow + (r0 + 8) * DM + col) = v1;
        }
    }
}

__global__ __launch_bounds__(256)
void proj_kernel(const float* __restrict__ q, const float* __restrict__ k,
                 const float* __restrict__ v, const float* __restrict__ bias)
{
    const int bm  = blockIdx.y;        // 0..383
    const int sel = bm >> 7;
    const float* A = (sel == 0) ? q : ((sel == 1) ? k : v);
    const int rowblk = bm & 127;
    gemm_body(A + (size_t)rowblk * 128 * DM, bias,
              g_proj + ((size_t)sel * MTOT + (size_t)rowblk * 128) * DM,
              blockIdx.x);
}

__global__ __launch_bounds__(256)
void final_kernel(const float* __restrict__ bias, float* __restrict__ out)
{
    gemm_body(g_concat + (size_t)blockIdx.y * 128 * DM, bias,
              out + (size_t)blockIdx.y * 128 * DM, blockIdx.x);
}

// ---------------- per-token attention, register-tiled (proven) ----------------
#define SLP 68

__global__ __launch_bounds__(256)
void attn_kernel()
{
    const int pos = blockIdx.x;
    const int b   = pos >> 11;
    const int s   = pos & 2047;

    __shared__ float sq[DM];
    __shared__ float sk[DM];
    __shared__ float svT[DM];
    __shared__ float sL[HD * SLP];

    const int tid = threadIdx.x;
    const float* baseq = g_proj + (size_t)pos * DM;
    const float* basek = g_proj + ((size_t)MTOT + pos) * DM;
    const float* basev = g_proj + ((size_t)2 * MTOT + pos) * DM;

    reinterpret_cast<float4*>(sq)[tid] = reinterpret_cast<const float4*>(baseq)[tid];
    reinterpret_cast<float4*>(sk)[tid] = reinterpret_cast<const float4*>(basek)[tid];
    {
        float4 vv = reinterpret_cast<const float4*>(basev)[tid];
        int n0 = tid * 4;
        int h  = n0 >> 6;
        int e  = n0 & 63;
        svT[(e + 0) * NH + h] = vv.x;
        svT[(e + 1) * NH + h] = vv.y;
        svT[(e + 2) * NH + h] = vv.z;
        svT[(e + 3) * NH + h] = vv.w;
    }
    __syncthreads();

    {
        const int ty = tid >> 4;
        const int tx = tid & 15;
        float c[4][4];
#pragma unroll
        for (int i = 0; i < 4; ++i)
#pragma unroll
            for (int j = 0; j < 4; ++j) c[i][j] = 0.f;
#pragma unroll
        for (int h = 0; h < 16; ++h) {
            float4 qa = *reinterpret_cast<const float4*>(&sq[h * HD + ty * 4]);
            float4 kb = *reinterpret_cast<const float4*>(&sk[h * HD + tx * 4]);
            const float qv[4] = { qa.x, qa.y, qa.z, qa.w };
            const float kv[4] = { kb.x, kb.y, kb.z, kb.w };
#pragma unroll
            for (int i = 0; i < 4; ++i)
#pragma unroll
                for (int j = 0; j < 4; ++j)
                    c[i][j] += qv[i] * kv[j];
        }
#pragma unroll
        for (int i = 0; i < 4; ++i) {
            float4 v = { c[i][0] * 0.125f, c[i][1] * 0.125f,
                         c[i][2] * 0.125f, c[i][3] * 0.125f };
            *reinterpret_cast<float4*>(&sL[(ty * 4 + i) * SLP + tx * 4]) = v;
        }
    }
    __syncthreads();

    {
        const int row = tid >> 2;
        const int sub = tid & 3;
        float* rp = sL + row * SLP + sub * 16;
        float4 v0 = *reinterpret_cast<float4*>(rp + 0);
        float4 v1 = *reinterpret_cast<float4*>(rp + 4);
        float4 v2 = *reinterpret_cast<float4*>(rp + 8);
        float4 v3 = *reinterpret_cast<float4*>(rp + 12);
        float m = fmaxf(fmaxf(fmaxf(v0.x, v0.y), fmaxf(v0.z, v0.w)),
                        fmaxf(fmaxf(v1.x, v1.y), fmaxf(v1.z, v1.w)));
        m = fmaxf(m, fmaxf(fmaxf(fmaxf(v2.x, v2.y), fmaxf(v2.z, v2.w)),
                           fmaxf(fmaxf(v3.x, v3.y), fmaxf(v3.z, v3.w))));
        m = fmaxf(m, __shfl_xor_sync(0xFFFFFFFFu, m, 1));
        m = fmaxf(m, __shfl_xor_sync(0xFFFFFFFFu, m, 2));
        v0.x = __expf(v0.x - m); v0.y = __expf(v0.y - m);
        v0.z = __expf(v0.z - m); v0.w = __expf(v0.w - m);
        v1.x = __expf(v1.x - m); v1.y = __expf(v1.y - m);
        v1.z = __expf(v1.z - m); v1.w = __expf(v1.w - m);
        v2.x = __expf(v2.x - m); v2.y = __expf(v2.y - m);
        v2.z = __expf(v2.z - m); v2.w = __expf(v2.w - m);
        v3.x = __expf(v3.x - m); v3.y = __expf(v3.y - m);
        v3.z = __expf(v3.z - m); v3.w = __expf(v3.w - m);
        float sum = (v0.x + v0.y + v0.z + v0.w) + (v1.x + v1.y + v1.z + v1.w)
                  + (v2.x + v2.y + v2.z + v2.w) + (v3.x + v3.y + v3.z + v3.w);
        sum += __shfl_xor_sync(0xFFFFFFFFu, sum, 1);
        sum += __shfl_xor_sync(0xFFFFFFFFu, sum, 2);
        float inv = 1.f / sum;
        v0.x *= inv; v0.y *= inv; v0.z *= inv; v0.w *= inv;
        v1.x *= inv; v1.y *= inv; v1.z *= inv; v1.w *= inv;
        v2.x *= inv; v2.y *= inv; v2.z *= inv; v2.w *= inv;
        v3.x *= inv; v3.y *= inv; v3.z *= inv; v3.w *= inv;
        *reinterpret_cast<float4*>(rp + 0)  = v0;
        *reinterpret_cast<float4*>(rp + 4)  = v1;
        *reinterpret_cast<float4*>(rp + 8)  = v2;
        *reinterpret_cast<float4*>(rp + 12) = v3;
    }
    __syncthreads();

    {
        const int d  = tid >> 2;
        const int hq = tid & 3;
        float4 acc = { 0.f, 0.f, 0.f, 0.f };
        const float* lrow = sL + d * SLP;
#pragma unroll 8
        for (int e = 0; e < 64; ++e) {
            float p = lrow[e];
            float4 vv = *reinterpret_cast<const float4*>(&svT[e * NH + hq * 4]);
            acc.x += p * vv.x; acc.y += p * vv.y;
            acc.z += p * vv.z; acc.w += p * vv.w;
        }
        const int srow = s >> 6;
        const int scol = s & 63;
        float* dst = g_concat + (size_t)b * SEQ * DM
                   + (size_t)(d * 32 + srow) * DM + scol * NH + hq * 4;
        *reinterpret_cast<float4*>(dst) = acc;
    }
}

// ---------------------------------------------------------------------------
extern "C" void kernel_launch(void* const* d_in, const int* in_sizes, int n_in,
                              void* d_out, int out_size)
{
    const float* q = (const float*)d_in[0];
    const float* k = (const float*)d_in[1];
    const float* v = (const float*)d_in[2];
    const float* W = (const float*)d_in[3];
    const float* b = (const float*)d_in[4];
    float* out = (float*)d_out;

    convert_w<<<DM * DM / 4 / 256, 256>>>(W);

    proj_kernel<<<dim3(8, 384), 256>>>(q, k, v, b);

    attn_kernel<<<MTOT, 256>>>();

    final_kernel<<<dim3(8, 128), 256>>>(b, out);
}